// round 14
// baseline (speedup 1.0000x reference)
#include <cuda_runtime.h>

// ---------------------------------------------------------------------------
// GCN 2-layer: out = A_hat(relu(A_hat(x@W1)+b1) @ W2) + b2
// CSR-gather design (R13, 213us) + R14: grid-fused overlap of the FMA-bound
// gemm1 with the LTS-atomic-bound deg/scatter passes (resource-disjoint).
// ---------------------------------------------------------------------------

#define MAX_N 100000
#define MAX_E 3200000
#define F_IN  512
#define HID   16
#define CLS   7

#define SCAN_B 1024
#define MAX_PART 128   // ceil(MAX_N / SCAN_B) = 98

// Scratch (device globals: allocation-free rule).
__device__ __align__(16) int   g_degi  [MAX_N];
__device__ __align__(16) float g_dinv  [MAX_N];
__device__ __align__(16) int   g_rowptr[MAX_N + 1];
__device__ __align__(16) int   g_cursor[MAX_N];
__device__ __align__(16) int   g_part  [MAX_PART];
__device__ __align__(16) int   g_partpre[MAX_PART];
__device__ __align__(16) int2  g_csr   [MAX_E];       // {src, __float_as_int(w)}
__device__ __align__(16) float g_h     [MAX_N * HID]; // x @ W1
__device__ __align__(16) float g_hagg  [MAX_N * HID]; // aggregated layer-1
__device__ __align__(16) float g_h2    [MAX_N * CLS]; // relu(hagg+b1) @ W2
__device__ int g_is64;                                 // edge_index dtype flag

// ---------------------------------------------------------------------------
// dtype probe: int64 interpretation valid iff all sampled values in [0, n).
__global__ void k_detect(const void* __restrict__ ei, int n) {
    if (blockIdx.x == 0 && threadIdx.x == 0) {
        const long long* p = (const long long*)ei;
        int ok = 1;
        #pragma unroll 1
        for (int i = 0; i < 64; i++) {
            long long v = p[i];
            if (v < 0 || v >= (long long)n) { ok = 0; break; }
        }
        g_is64 = ok;
    }
}

__device__ __forceinline__ void edge_sd(const void* __restrict__ ei,
                                        int e, int E, int& s, int& d) {
    if (g_is64) {
        const long long* p = (const long long*)ei;
        s = (int)p[e];
        d = (int)p[e + E];
    } else {
        const int* p = (const int*)ei;
        s = p[e];
        d = p[e + E];
    }
}

// ---------------------------------------------------------------------------
__global__ void k_zero_deg(int n) {
    int i = blockIdx.x * blockDim.x + threadIdx.x;
    if (i < n) g_degi[i] = 0;
}

// ---------------------------------------------------------------------------
// GEMM1 body (R8-proven): one 256-row block of h = x @ W1. Called from the
// fused kernels with an explicit block-row index.
#define G1_ROWS 256
#define G1_KC   32
#define G1_XS_STRIDE 36   // 32 + 4 pad

__device__ __forceinline__ void gemm1_block(
    const float* __restrict__ x, const float* __restrict__ W1,
    int n, int blk)
{
    __shared__ __align__(16) float xs[G1_ROWS * G1_XS_STRIDE];  // 36 KB
    __shared__ __align__(16) float Wc[G1_KC * HID];             // 2 KB

    const int t    = threadIdx.x;
    const int rg   = t >> 2;
    const int cg   = t & 3;
    const int row0 = blk * G1_ROWS;

    float acc[4][4];
    #pragma unroll
    for (int i = 0; i < 4; i++)
        #pragma unroll
        for (int j = 0; j < 4; j++) acc[i][j] = 0.0f;

    const float4* x4 = (const float4*)x;
    const float4* W4 = (const float4*)W1;

    for (int kc = 0; kc < F_IN / G1_KC; kc++) {
        __syncthreads();
        #pragma unroll
        for (int i = 0; i < 8; i++) {
            int idx = t + i * 256;
            int r   = idx >> 3;
            int q   = idx & 7;
            int gr  = row0 + r;
            float4 v = make_float4(0.f, 0.f, 0.f, 0.f);
            if (gr < n) v = x4[gr * (F_IN / 4) + kc * (G1_KC / 4) + q];
            *(float4*)&xs[r * G1_XS_STRIDE + q * 4] = v;
        }
        if (t < 128) ((float4*)Wc)[t] = W4[kc * (G1_KC * HID / 4) + t];
        __syncthreads();

        #pragma unroll
        for (int k4 = 0; k4 < G1_KC / 4; k4++) {
            const int k = k4 * 4;
            float4 w0 = ((const float4*)Wc)[(k + 0) * 4 + cg];
            float4 w1 = ((const float4*)Wc)[(k + 1) * 4 + cg];
            float4 w2 = ((const float4*)Wc)[(k + 2) * 4 + cg];
            float4 w3 = ((const float4*)Wc)[(k + 3) * 4 + cg];
            #pragma unroll
            for (int i = 0; i < 4; i++) {
                const int r = rg + 64 * i;
                float4 xv = *(const float4*)&xs[r * G1_XS_STRIDE + k];
                acc[i][0] += xv.x * w0.x + xv.y * w1.x + xv.z * w2.x + xv.w * w3.x;
                acc[i][1] += xv.x * w0.y + xv.y * w1.y + xv.z * w2.y + xv.w * w3.y;
                acc[i][2] += xv.x * w0.z + xv.y * w1.z + xv.z * w2.z + xv.w * w3.z;
                acc[i][3] += xv.x * w0.w + xv.y * w1.w + xv.z * w2.w + xv.w * w3.w;
            }
        }
    }

    #pragma unroll
    for (int i = 0; i < 4; i++) {
        const int r = row0 + rg + 64 * i;
        if (r < n)
            *(float4*)&g_h[r * HID + cg * 4] =
                make_float4(acc[i][0], acc[i][1], acc[i][2], acc[i][3]);
    }
}

// ---------------------------------------------------------------------------
// Fused kernel A: blocks [0, gb) run gemm1 on rows [0, gb*256);
// blocks [gb, gb+degb) run the dst-degree histogram (scalar, 1 edge/thread).
__global__ void __launch_bounds__(256) k_fuseA(
    const float* __restrict__ x, const float* __restrict__ W1,
    const void* __restrict__ ei, int E, int n, int gb)
{
    int b = blockIdx.x;
    if (b < gb) {
        gemm1_block(x, W1, n, b);
    } else {
        int e = (b - gb) * 256 + threadIdx.x;
        if (e >= E) return;
        int d;
        if (g_is64) d = (int)((const long long*)ei)[e + E];
        else        d = ((const int*)ei)[e + E];
        if ((unsigned)d < (unsigned)n) atomicAdd(&g_degi[d], 1);
    }
}

// ---------------------------------------------------------------------------
// Multi-block exclusive scan, phase 1: per-block (1024-chunk) sums.
__global__ void __launch_bounds__(SCAN_B) k_part(int n) {
    __shared__ int sd[SCAN_B];
    int t = threadIdx.x;
    int i = blockIdx.x * SCAN_B + t;
    sd[t] = (i < n) ? g_degi[i] : 0;
    __syncthreads();
    #pragma unroll
    for (int off = SCAN_B / 2; off > 0; off >>= 1) {
        if (t < off) sd[t] += sd[t + off];
        __syncthreads();
    }
    if (t == 0) g_part[blockIdx.x] = sd[0];
}

// Phase 2: single small block scans the partials (nb <= MAX_PART).
__global__ void __launch_bounds__(MAX_PART) k_scanpart(int nb, int n) {
    __shared__ int sd[MAX_PART];
    int t = threadIdx.x;
    int v = (t < nb) ? g_part[t] : 0;
    sd[t] = v;
    __syncthreads();
    #pragma unroll
    for (int off = 1; off < MAX_PART; off <<= 1) {
        int a = sd[t];
        int b = (t >= off) ? sd[t - off] : 0;
        __syncthreads();
        sd[t] = a + b;
        __syncthreads();
    }
    if (t < nb) g_partpre[t] = sd[t] - v;       // exclusive prefix
    if (t == MAX_PART - 1) g_rowptr[n] = sd[MAX_PART - 1];
}

// Phase 3: in-block exclusive scan + block offset; fused dinv.
__global__ void __launch_bounds__(SCAN_B) k_scanfinal(int n) {
    __shared__ int sd[SCAN_B];
    int t = threadIdx.x;
    int i = blockIdx.x * SCAN_B + t;
    int v = (i < n) ? g_degi[i] : 0;
    sd[t] = v;
    __syncthreads();
    #pragma unroll
    for (int off = 1; off < SCAN_B; off <<= 1) {
        int a = sd[t];
        int b = (t >= off) ? sd[t - off] : 0;
        __syncthreads();
        sd[t] = a + b;
        __syncthreads();
    }
    if (i < n) {
        int pos = g_partpre[blockIdx.x] + sd[t] - v;
        g_rowptr[i] = pos;
        g_cursor[i] = pos;
        g_dinv[i]   = rsqrtf((float)(v + 1));   // +1 self loop
    }
}

// ---------------------------------------------------------------------------
// Fused kernel B: blocks [0, gb2) run gemm1 on rows [(gb1+b)*256);
// blocks [gb2, gb2+scatb) scatter edges into CSR (scalar, 1 edge/thread).
__global__ void __launch_bounds__(256) k_fuseB(
    const float* __restrict__ x, const float* __restrict__ W1,
    const void* __restrict__ ei, int E, int n, int gb1, int gb2)
{
    int b = blockIdx.x;
    if (b < gb2) {
        gemm1_block(x, W1, n, gb1 + b);
    } else {
        int e = (b - gb2) * 256 + threadIdx.x;
        if (e >= E) return;
        int s, d;
        edge_sd(ei, e, E, s, d);
        if ((unsigned)s >= (unsigned)n || (unsigned)d >= (unsigned)n) return;
        float w = g_dinv[s] * g_dinv[d];
        int pos = atomicAdd(&g_cursor[d], 1);
        if (pos < MAX_E) g_csr[pos] = make_int2(s, __float_as_int(w));
    }
}

// ---------------------------------------------------------------------------
// Layer-1 aggregation (gather, no atomics): 4 lanes/node, float4 per lane.
__global__ void __launch_bounds__(256) k_agg1(int n)
{
    int id   = blockIdx.x * blockDim.x + threadIdx.x;
    int node = id >> 2;
    if (node >= n) return;
    int q = (id & 3) * 4;   // feature group: 0,4,8,12

    int j   = g_rowptr[node];
    int end = g_rowptr[node + 1];

    float4 a0 = make_float4(0.f, 0.f, 0.f, 0.f);
    float4 a1 = make_float4(0.f, 0.f, 0.f, 0.f);
    for (; j + 1 < end; j += 2) {
        int2 r0 = g_csr[j];
        int2 r1 = g_csr[j + 1];
        float  w0 = __int_as_float(r0.y);
        float  w1 = __int_as_float(r1.y);
        float4 h0 = *(const float4*)&g_h[r0.x * HID + q];
        float4 h1 = *(const float4*)&g_h[r1.x * HID + q];
        a0.x = fmaf(h0.x, w0, a0.x); a0.y = fmaf(h0.y, w0, a0.y);
        a0.z = fmaf(h0.z, w0, a0.z); a0.w = fmaf(h0.w, w0, a0.w);
        a1.x = fmaf(h1.x, w1, a1.x); a1.y = fmaf(h1.y, w1, a1.y);
        a1.z = fmaf(h1.z, w1, a1.z); a1.w = fmaf(h1.w, w1, a1.w);
    }
    if (j < end) {
        int2 r = g_csr[j];
        float  w = __int_as_float(r.y);
        float4 h = *(const float4*)&g_h[r.x * HID + q];
        a0.x = fmaf(h.x, w, a0.x); a0.y = fmaf(h.y, w, a0.y);
        a0.z = fmaf(h.z, w, a0.z); a0.w = fmaf(h.w, w, a0.w);
    }

    float di = g_dinv[node];
    float sw = di * di;
    float4 hv = *(const float4*)&g_h[node * HID + q];
    float4 r;
    r.x = a0.x + a1.x + hv.x * sw;
    r.y = a0.y + a1.y + hv.y * sw;
    r.z = a0.z + a1.z + hv.z * sw;
    r.w = a0.w + a1.w + hv.w * sw;
    *(float4*)&g_hagg[node * HID + q] = r;
}

// ---------------------------------------------------------------------------
// GEMM2: h2 = relu(hagg + b1) @ W2
__global__ void __launch_bounds__(256) k_gemm2(
    const float* __restrict__ b1, const float* __restrict__ W2, int n)
{
    __shared__ float W2s[HID * CLS];
    __shared__ float b1s[HID];
    int t = threadIdx.x;
    if (t < HID * CLS) W2s[t] = W2[t];
    if (t < HID)       b1s[t] = b1[t];
    __syncthreads();

    int i = blockIdx.x * blockDim.x + t;
    if (i >= n) return;

    float v[HID];
    #pragma unroll
    for (int q = 0; q < 4; q++) {
        float4 hv = *(const float4*)&g_hagg[i * HID + q * 4];
        v[q * 4 + 0] = fmaxf(hv.x + b1s[q * 4 + 0], 0.0f);
        v[q * 4 + 1] = fmaxf(hv.y + b1s[q * 4 + 1], 0.0f);
        v[q * 4 + 2] = fmaxf(hv.z + b1s[q * 4 + 2], 0.0f);
        v[q * 4 + 3] = fmaxf(hv.w + b1s[q * 4 + 3], 0.0f);
    }

    float o[CLS];
    #pragma unroll
    for (int c2 = 0; c2 < CLS; c2++) o[c2] = 0.0f;
    #pragma unroll
    for (int c = 0; c < HID; c++) {
        float xv = v[c];
        #pragma unroll
        for (int c2 = 0; c2 < CLS; c2++) o[c2] += xv * W2s[c * CLS + c2];
    }

    #pragma unroll
    for (int c2 = 0; c2 < CLS; c2++) g_h2[i * CLS + c2] = o[c2];
}

// ---------------------------------------------------------------------------
// Layer-2 aggregation (gather): 8 lanes per node (7 used).
__global__ void __launch_bounds__(256) k_agg2(
    const float* __restrict__ b2, float* __restrict__ out, int n)
{
    int id   = blockIdx.x * blockDim.x + threadIdx.x;
    int node = id >> 3;
    if (node >= n) return;
    int c = id & 7;
    if (c >= CLS) return;

    int j   = g_rowptr[node];
    int end = g_rowptr[node + 1];

    float acc0 = 0.0f, acc1 = 0.0f;
    for (; j + 1 < end; j += 2) {
        int2 r0 = g_csr[j];
        int2 r1 = g_csr[j + 1];
        acc0 = fmaf(g_h2[r0.x * CLS + c], __int_as_float(r0.y), acc0);
        acc1 = fmaf(g_h2[r1.x * CLS + c], __int_as_float(r1.y), acc1);
    }
    if (j < end) {
        int2 r = g_csr[j];
        acc0 = fmaf(g_h2[r.x * CLS + c], __int_as_float(r.y), acc0);
    }

    float di = g_dinv[node];
    out[node * CLS + c] = acc0 + acc1 + g_h2[node * CLS + c] * di * di + b2[c];
}

// ---------------------------------------------------------------------------
extern "C" void kernel_launch(void* const* d_in, const int* in_sizes, int n_in,
                              void* d_out, int out_size)
{
    // ---- identify inputs by element count ----
    int ix = -1, ie = -1, iw1 = -1, ib1 = -1, iw2 = -1, ib2 = -1;
    for (int i = 0; i < n_in; i++)
        if (ix < 0 || in_sizes[i] > in_sizes[ix]) ix = i;
    for (int i = 0; i < n_in; i++) {
        if (i == ix) continue;
        if (ie < 0 || in_sizes[i] > in_sizes[ie]) ie = i;
    }
    for (int i = 0; i < n_in; i++) {
        if (i == ix || i == ie) continue;
        if (in_sizes[i] == F_IN * HID) iw1 = i;
        else if (in_sizes[i] == HID * CLS) iw2 = i;
        else if (in_sizes[i] == HID) ib1 = i;
        else if (in_sizes[i] == CLS) ib2 = i;
    }
    if (ix < 0 || ie < 0 || iw1 < 0 || ib1 < 0 || iw2 < 0 || ib2 < 0) {
        ix = 0; ie = 1; iw1 = 2; ib1 = 3; iw2 = 4; ib2 = 5;
    }

    const float* x  = (const float*)d_in[ix];
    const void*  ei = d_in[ie];
    const float* W1 = (const float*)d_in[iw1];
    const float* b1 = (const float*)d_in[ib1];
    const float* W2 = (const float*)d_in[iw2];
    const float* b2 = (const float*)d_in[ib2];
    float* out = (float*)d_out;

    const int n = in_sizes[ix] / F_IN;   // 100000
    const int E = in_sizes[ie] / 2;      // 3200000

    const int TB = 256;
    const int nb = (n + SCAN_B - 1) / SCAN_B;         // 98
    const int gemm_blocks = (n + G1_ROWS - 1) / G1_ROWS;   // 391
    const int edge_blocks = (E + TB - 1) / TB;              // 12500
    // Split gemm across the two fused phases ~ proportional to deg/scatter cost.
    int gb1 = (gemm_blocks * 2) / 5;        // ~40% with the deg pass
    int gb2 = gemm_blocks - gb1;            // ~60% with the scatter pass

    k_detect<<<1, 32>>>(ei, n);
    k_zero_deg<<<(n + TB - 1) / TB, TB>>>(n);

    // Phase A: gemm1 (part 1) || deg histogram
    k_fuseA<<<gb1 + edge_blocks, TB>>>(x, W1, ei, E, n, gb1);

    // scan
    k_part<<<nb, SCAN_B>>>(n);
    k_scanpart<<<1, MAX_PART>>>(nb, n);
    k_scanfinal<<<nb, SCAN_B>>>(n);

    // Phase B: gemm1 (part 2) || scatter
    k_fuseB<<<gb2 + edge_blocks, TB>>>(x, W1, ei, E, n, gb1, gb2);

    // layer 1 aggregation
    {
        long long work = (long long)n * 4;
        k_agg1<<<(int)((work + TB - 1) / TB), TB>>>(n);
    }

    // layer 2
    k_gemm2<<<(n + TB - 1) / TB, TB>>>(b1, W2, n);
    {
        long long work = (long long)n * 8;
        k_agg2<<<(int)((work + TB - 1) / TB), TB>>>(b2, out, n);
    }
}

// round 15
// speedup vs baseline: 1.0708x; 1.0708x over previous
#include <cuda_runtime.h>

// ---------------------------------------------------------------------------
// GCN 2-layer: out = A_hat(relu(A_hat(x@W1)+b1) @ W2) + b2
// CSR-gather design (R13 baseline, 213us). R15: gemm1 moved to launch slot 4
// (profiler captures the 4th launch), g_h2 padded to stride 8 and k_agg2
// vectorized to 2 lanes/node x float4.
// ---------------------------------------------------------------------------

#define MAX_N 100000
#define MAX_E 3200000
#define F_IN  512
#define HID   16
#define CLS   7
#define HID2  8     // padded h2 row stride (CLS=7 -> 8 for float4 access)

#define SCAN_B 1024
#define MAX_PART 128   // ceil(MAX_N / SCAN_B) = 98

// Scratch (device globals: allocation-free rule).
__device__ __align__(16) int   g_degi  [MAX_N];
__device__ __align__(16) float g_dinv  [MAX_N];
__device__ __align__(16) int   g_rowptr[MAX_N + 1];
__device__ __align__(16) int   g_cursor[MAX_N];
__device__ __align__(16) int   g_part  [MAX_PART];
__device__ __align__(16) int   g_partpre[MAX_PART];
__device__ __align__(16) int2  g_csr   [MAX_E];        // {src, __float_as_int(w)}
__device__ __align__(16) float g_h     [MAX_N * HID];  // x @ W1
__device__ __align__(16) float g_hagg  [MAX_N * HID];  // aggregated layer-1
__device__ __align__(16) float g_h2    [MAX_N * HID2]; // relu(hagg+b1) @ W2, padded
__device__ int g_is64;                                  // edge_index dtype flag

// ---------------------------------------------------------------------------
// dtype probe: int64 interpretation valid iff all sampled values in [0, n).
__global__ void k_detect(const void* __restrict__ ei, int n) {
    if (blockIdx.x == 0 && threadIdx.x == 0) {
        const long long* p = (const long long*)ei;
        int ok = 1;
        #pragma unroll 1
        for (int i = 0; i < 64; i++) {
            long long v = p[i];
            if (v < 0 || v >= (long long)n) { ok = 0; break; }
        }
        g_is64 = ok;
    }
}

__device__ __forceinline__ void edge_sd(const void* __restrict__ ei,
                                        int e, int E, int& s, int& d) {
    if (g_is64) {
        const long long* p = (const long long*)ei;
        s = (int)p[e];
        d = (int)p[e + E];
    } else {
        const int* p = (const int*)ei;
        s = p[e];
        d = p[e + E];
    }
}

// ---------------------------------------------------------------------------
__global__ void k_zero_deg(int n) {
    int i = blockIdx.x * blockDim.x + threadIdx.x;
    if (i < n) g_degi[i] = 0;
}

// int histogram of dst (scalar, 1 edge/thread — proven)
__global__ void k_deg(const void* __restrict__ ei, int E, int n) {
    int e = blockIdx.x * blockDim.x + threadIdx.x;
    if (e >= E) return;
    int d;
    if (g_is64) d = (int)((const long long*)ei)[e + E];
    else        d = ((const int*)ei)[e + E];
    if ((unsigned)d < (unsigned)n) atomicAdd(&g_degi[d], 1);
}

// ---------------------------------------------------------------------------
// Multi-block exclusive scan, phase 1: per-block (1024-chunk) sums.
__global__ void __launch_bounds__(SCAN_B) k_part(int n) {
    __shared__ int sd[SCAN_B];
    int t = threadIdx.x;
    int i = blockIdx.x * SCAN_B + t;
    sd[t] = (i < n) ? g_degi[i] : 0;
    __syncthreads();
    #pragma unroll
    for (int off = SCAN_B / 2; off > 0; off >>= 1) {
        if (t < off) sd[t] += sd[t + off];
        __syncthreads();
    }
    if (t == 0) g_part[blockIdx.x] = sd[0];
}

// Phase 2: single small block scans the partials (nb <= MAX_PART).
__global__ void __launch_bounds__(MAX_PART) k_scanpart(int nb, int n) {
    __shared__ int sd[MAX_PART];
    int t = threadIdx.x;
    int v = (t < nb) ? g_part[t] : 0;
    sd[t] = v;
    __syncthreads();
    #pragma unroll
    for (int off = 1; off < MAX_PART; off <<= 1) {
        int a = sd[t];
        int b = (t >= off) ? sd[t - off] : 0;
        __syncthreads();
        sd[t] = a + b;
        __syncthreads();
    }
    if (t < nb) g_partpre[t] = sd[t] - v;       // exclusive prefix
    if (t == MAX_PART - 1) g_rowptr[n] = sd[MAX_PART - 1];
}

// Phase 3: in-block exclusive scan + block offset; fused dinv.
__global__ void __launch_bounds__(SCAN_B) k_scanfinal(int n) {
    __shared__ int sd[SCAN_B];
    int t = threadIdx.x;
    int i = blockIdx.x * SCAN_B + t;
    int v = (i < n) ? g_degi[i] : 0;
    sd[t] = v;
    __syncthreads();
    #pragma unroll
    for (int off = 1; off < SCAN_B; off <<= 1) {
        int a = sd[t];
        int b = (t >= off) ? sd[t - off] : 0;
        __syncthreads();
        sd[t] = a + b;
        __syncthreads();
    }
    if (i < n) {
        int pos = g_partpre[blockIdx.x] + sd[t] - v;
        g_rowptr[i] = pos;
        g_cursor[i] = pos;
        g_dinv[i]   = rsqrtf((float)(v + 1));   // +1 self loop
    }
}

// ---------------------------------------------------------------------------
// Scatter edges into CSR slots (scalar, 1 edge/thread — proven).
__global__ void k_scatter(const void* __restrict__ ei, int E, int n) {
    int e = blockIdx.x * blockDim.x + threadIdx.x;
    if (e >= E) return;
    int s, d;
    edge_sd(ei, e, E, s, d);
    if ((unsigned)s >= (unsigned)n || (unsigned)d >= (unsigned)n) return;
    float w = g_dinv[s] * g_dinv[d];
    int pos = atomicAdd(&g_cursor[d], 1);
    if (pos < MAX_E) g_csr[pos] = make_int2(s, __float_as_int(w));
}

// ---------------------------------------------------------------------------
// GEMM1 (proven R8 version): h = x @ W1   (M=n, K=512, N=16)
#define G1_ROWS 256
#define G1_KC   32
#define G1_XS_STRIDE 36   // 32 + 4 pad

__global__ void __launch_bounds__(256) k_gemm1(
    const float* __restrict__ x, const float* __restrict__ W1, int n)
{
    __shared__ __align__(16) float xs[G1_ROWS * G1_XS_STRIDE];  // 36 KB
    __shared__ __align__(16) float Wc[G1_KC * HID];             // 2 KB

    const int t    = threadIdx.x;
    const int rg   = t >> 2;
    const int cg   = t & 3;
    const int row0 = blockIdx.x * G1_ROWS;

    float acc[4][4];
    #pragma unroll
    for (int i = 0; i < 4; i++)
        #pragma unroll
        for (int j = 0; j < 4; j++) acc[i][j] = 0.0f;

    const float4* x4 = (const float4*)x;
    const float4* W4 = (const float4*)W1;

    for (int kc = 0; kc < F_IN / G1_KC; kc++) {
        __syncthreads();
        #pragma unroll
        for (int i = 0; i < 8; i++) {
            int idx = t + i * 256;
            int r   = idx >> 3;
            int q   = idx & 7;
            int gr  = row0 + r;
            float4 v = make_float4(0.f, 0.f, 0.f, 0.f);
            if (gr < n) v = x4[gr * (F_IN / 4) + kc * (G1_KC / 4) + q];
            *(float4*)&xs[r * G1_XS_STRIDE + q * 4] = v;
        }
        if (t < 128) ((float4*)Wc)[t] = W4[kc * (G1_KC * HID / 4) + t];
        __syncthreads();

        #pragma unroll
        for (int k4 = 0; k4 < G1_KC / 4; k4++) {
            const int k = k4 * 4;
            float4 w0 = ((const float4*)Wc)[(k + 0) * 4 + cg];
            float4 w1 = ((const float4*)Wc)[(k + 1) * 4 + cg];
            float4 w2 = ((const float4*)Wc)[(k + 2) * 4 + cg];
            float4 w3 = ((const float4*)Wc)[(k + 3) * 4 + cg];
            #pragma unroll
            for (int i = 0; i < 4; i++) {
                const int r = rg + 64 * i;
                float4 xv = *(const float4*)&xs[r * G1_XS_STRIDE + k];
                acc[i][0] += xv.x * w0.x + xv.y * w1.x + xv.z * w2.x + xv.w * w3.x;
                acc[i][1] += xv.x * w0.y + xv.y * w1.y + xv.z * w2.y + xv.w * w3.y;
                acc[i][2] += xv.x * w0.z + xv.y * w1.z + xv.z * w2.z + xv.w * w3.z;
                acc[i][3] += xv.x * w0.w + xv.y * w1.w + xv.z * w2.w + xv.w * w3.w;
            }
        }
    }

    #pragma unroll
    for (int i = 0; i < 4; i++) {
        const int r = row0 + rg + 64 * i;
        if (r < n)
            *(float4*)&g_h[r * HID + cg * 4] =
                make_float4(acc[i][0], acc[i][1], acc[i][2], acc[i][3]);
    }
}

// ---------------------------------------------------------------------------
// Layer-1 aggregation (gather, no atomics): 4 lanes/node, float4 per lane.
__global__ void __launch_bounds__(256) k_agg1(int n)
{
    int id   = blockIdx.x * blockDim.x + threadIdx.x;
    int node = id >> 2;
    if (node >= n) return;
    int q = (id & 3) * 4;   // feature group: 0,4,8,12

    int j   = g_rowptr[node];
    int end = g_rowptr[node + 1];

    float4 a0 = make_float4(0.f, 0.f, 0.f, 0.f);
    float4 a1 = make_float4(0.f, 0.f, 0.f, 0.f);
    for (; j + 1 < end; j += 2) {
        int2 r0 = g_csr[j];
        int2 r1 = g_csr[j + 1];
        float  w0 = __int_as_float(r0.y);
        float  w1 = __int_as_float(r1.y);
        float4 h0 = *(const float4*)&g_h[r0.x * HID + q];
        float4 h1 = *(const float4*)&g_h[r1.x * HID + q];
        a0.x = fmaf(h0.x, w0, a0.x); a0.y = fmaf(h0.y, w0, a0.y);
        a0.z = fmaf(h0.z, w0, a0.z); a0.w = fmaf(h0.w, w0, a0.w);
        a1.x = fmaf(h1.x, w1, a1.x); a1.y = fmaf(h1.y, w1, a1.y);
        a1.z = fmaf(h1.z, w1, a1.z); a1.w = fmaf(h1.w, w1, a1.w);
    }
    if (j < end) {
        int2 r = g_csr[j];
        float  w = __int_as_float(r.y);
        float4 h = *(const float4*)&g_h[r.x * HID + q];
        a0.x = fmaf(h.x, w, a0.x); a0.y = fmaf(h.y, w, a0.y);
        a0.z = fmaf(h.z, w, a0.z); a0.w = fmaf(h.w, w, a0.w);
    }

    float di = g_dinv[node];
    float sw = di * di;
    float4 hv = *(const float4*)&g_h[node * HID + q];
    float4 r;
    r.x = a0.x + a1.x + hv.x * sw;
    r.y = a0.y + a1.y + hv.y * sw;
    r.z = a0.z + a1.z + hv.z * sw;
    r.w = a0.w + a1.w + hv.w * sw;
    *(float4*)&g_hagg[node * HID + q] = r;
}

// ---------------------------------------------------------------------------
// GEMM2: h2 = relu(hagg + b1) @ W2  (h2 stored with padded stride HID2=8)
__global__ void __launch_bounds__(256) k_gemm2(
    const float* __restrict__ b1, const float* __restrict__ W2, int n)
{
    __shared__ float W2s[HID * CLS];
    __shared__ float b1s[HID];
    int t = threadIdx.x;
    if (t < HID * CLS) W2s[t] = W2[t];
    if (t < HID)       b1s[t] = b1[t];
    __syncthreads();

    int i = blockIdx.x * blockDim.x + t;
    if (i >= n) return;

    float v[HID];
    #pragma unroll
    for (int q = 0; q < 4; q++) {
        float4 hv = *(const float4*)&g_hagg[i * HID + q * 4];
        v[q * 4 + 0] = fmaxf(hv.x + b1s[q * 4 + 0], 0.0f);
        v[q * 4 + 1] = fmaxf(hv.y + b1s[q * 4 + 1], 0.0f);
        v[q * 4 + 2] = fmaxf(hv.z + b1s[q * 4 + 2], 0.0f);
        v[q * 4 + 3] = fmaxf(hv.w + b1s[q * 4 + 3], 0.0f);
    }

    float o[8];
    #pragma unroll
    for (int c2 = 0; c2 < 8; c2++) o[c2] = 0.0f;
    #pragma unroll
    for (int c = 0; c < HID; c++) {
        float xv = v[c];
        #pragma unroll
        for (int c2 = 0; c2 < CLS; c2++) o[c2] += xv * W2s[c * CLS + c2];
    }

    *(float4*)&g_h2[i * HID2 + 0] = make_float4(o[0], o[1], o[2], o[3]);
    *(float4*)&g_h2[i * HID2 + 4] = make_float4(o[4], o[5], o[6], 0.0f);
}

// ---------------------------------------------------------------------------
// Layer-2 aggregation v2 (gather): 2 lanes/node, float4 per lane over the
// padded h2 rows (cols 0-3 / 4-7, col 7 is zero padding).
__global__ void __launch_bounds__(256) k_agg2(
    const float* __restrict__ b2, float* __restrict__ out, int n)
{
    int id   = blockIdx.x * blockDim.x + threadIdx.x;
    int node = id >> 1;
    if (node >= n) return;
    int q = (id & 1) * 4;   // 0 or 4

    int j   = g_rowptr[node];
    int end = g_rowptr[node + 1];

    float4 a0 = make_float4(0.f, 0.f, 0.f, 0.f);
    float4 a1 = make_float4(0.f, 0.f, 0.f, 0.f);
    for (; j + 1 < end; j += 2) {
        int2 r0 = g_csr[j];
        int2 r1 = g_csr[j + 1];
        float  w0 = __int_as_float(r0.y);
        float  w1 = __int_as_float(r1.y);
        float4 h0 = *(const float4*)&g_h2[r0.x * HID2 + q];
        float4 h1 = *(const float4*)&g_h2[r1.x * HID2 + q];
        a0.x = fmaf(h0.x, w0, a0.x); a0.y = fmaf(h0.y, w0, a0.y);
        a0.z = fmaf(h0.z, w0, a0.z); a0.w = fmaf(h0.w, w0, a0.w);
        a1.x = fmaf(h1.x, w1, a1.x); a1.y = fmaf(h1.y, w1, a1.y);
        a1.z = fmaf(h1.z, w1, a1.z); a1.w = fmaf(h1.w, w1, a1.w);
    }
    if (j < end) {
        int2 r = g_csr[j];
        float  w = __int_as_float(r.y);
        float4 h = *(const float4*)&g_h2[r.x * HID2 + q];
        a0.x = fmaf(h.x, w, a0.x); a0.y = fmaf(h.y, w, a0.y);
        a0.z = fmaf(h.z, w, a0.z); a0.w = fmaf(h.w, w, a0.w);
    }

    float di = g_dinv[node];
    float sw = di * di;
    float4 hv = *(const float4*)&g_h2[node * HID2 + q];
    float r0 = a0.x + a1.x + hv.x * sw;
    float r1 = a0.y + a1.y + hv.y * sw;
    float r2 = a0.z + a1.z + hv.z * sw;
    float r3 = a0.w + a1.w + hv.w * sw;

    float* op = out + node * CLS;
    if (q == 0) {
        op[0] = r0 + b2[0];
        op[1] = r1 + b2[1];
        op[2] = r2 + b2[2];
        op[3] = r3 + b2[3];
    } else {
        op[4] = r0 + b2[4];
        op[5] = r1 + b2[5];
        op[6] = r2 + b2[6];
        // col 7 is padding; not stored
    }
}

// ---------------------------------------------------------------------------
extern "C" void kernel_launch(void* const* d_in, const int* in_sizes, int n_in,
                              void* d_out, int out_size)
{
    // ---- identify inputs by element count ----
    int ix = -1, ie = -1, iw1 = -1, ib1 = -1, iw2 = -1, ib2 = -1;
    for (int i = 0; i < n_in; i++)
        if (ix < 0 || in_sizes[i] > in_sizes[ix]) ix = i;
    for (int i = 0; i < n_in; i++) {
        if (i == ix) continue;
        if (ie < 0 || in_sizes[i] > in_sizes[ie]) ie = i;
    }
    for (int i = 0; i < n_in; i++) {
        if (i == ix || i == ie) continue;
        if (in_sizes[i] == F_IN * HID) iw1 = i;
        else if (in_sizes[i] == HID * CLS) iw2 = i;
        else if (in_sizes[i] == HID) ib1 = i;
        else if (in_sizes[i] == CLS) ib2 = i;
    }
    if (ix < 0 || ie < 0 || iw1 < 0 || ib1 < 0 || iw2 < 0 || ib2 < 0) {
        ix = 0; ie = 1; iw1 = 2; ib1 = 3; iw2 = 4; ib2 = 5;
    }

    const float* x  = (const float*)d_in[ix];
    const void*  ei = d_in[ie];
    const float* W1 = (const float*)d_in[iw1];
    const float* b1 = (const float*)d_in[ib1];
    const float* W2 = (const float*)d_in[iw2];
    const float* b2 = (const float*)d_in[ib2];
    float* out = (float*)d_out;

    const int n = in_sizes[ix] / F_IN;   // 100000
    const int E = in_sizes[ie] / 2;      // 3200000

    const int TB = 256;
    const int nb = (n + SCAN_B - 1) / SCAN_B;   // 98

    // Launch order note: the profiler captures the 4th launch -> k_gemm1
    // deliberately placed there (it is independent of the CSR chain).
    k_detect<<<1, 32>>>(ei, n);                                   // 1
    k_zero_deg<<<(n + TB - 1) / TB, TB>>>(n);                     // 2
    k_deg<<<(E + TB - 1) / TB, TB>>>(ei, E, n);                   // 3
    k_gemm1<<<(n + G1_ROWS - 1) / G1_ROWS, 256>>>(x, W1, n);      // 4  <- profiled
    k_part<<<nb, SCAN_B>>>(n);                                    // 5
    k_scanpart<<<1, MAX_PART>>>(nb, n);                           // 6
    k_scanfinal<<<nb, SCAN_B>>>(n);                               // 7
    k_scatter<<<(E + TB - 1) / TB, TB>>>(ei, E, n);               // 8

    // layer 1 aggregation
    {
        long long work = (long long)n * 4;
        k_agg1<<<(int)((work + TB - 1) / TB), TB>>>(n);           // 9
    }

    // layer 2
    k_gemm2<<<(n + TB - 1) / TB, TB>>>(b1, W2, n);                // 10
    {
        long long work = (long long)n * 2;
        k_agg2<<<(int)((work + TB - 1) / TB), TB>>>(b2, out, n);  // 11
    }
}